// round 1
// baseline (speedup 1.0000x reference)
#include <cuda_runtime.h>

// ---------------------------------------------------------------------------
// Attention block: out = proj( attn( qkv(x) ) )
//   x:[2,2048,1024]  w_attn:[1024,3072]  w_proj:[1024,1024]
//   H=16 heads, hd=64, scale=1/8, additive mask applied twice (it's zeros in
//   the dataset but we honor the reference formula).
// Scratch lives in __device__ globals (no allocations anywhere).
// ---------------------------------------------------------------------------

#define T_SEQ 2048
#define D_MODEL 1024
#define BT_ROWS 4096            // B*T

__device__ float g_qkv[(size_t)BT_ROWS * 3072];   // 50 MB
__device__ float g_att[(size_t)BT_ROWS * 1024];   // 16 MB

// ---------------------------------------------------------------------------
// SGEMM: C[M,N] = A[M,K] @ B[K,N] + bias[N]
// 128x128 block tile, BK=8, 256 threads, 8x8 per thread (4+4 split register
// tiles so all smem reads are contiguous float4 -> conflict-free).
// M,N,K all multiples of 128/8 here, so no bounds checks.
// ---------------------------------------------------------------------------
__global__ __launch_bounds__(256) void sgemm_bias(
    const float* __restrict__ A, const float* __restrict__ B,
    const float* __restrict__ bias, float* __restrict__ C,
    int M, int N, int K)
{
    __shared__ float As[8][128];   // transposed A tile: As[k][m]
    __shared__ float Bs[8][128];   // Bs[k][n]

    const int tid  = threadIdx.x;
    const int bm   = blockIdx.y * 128;
    const int bn   = blockIdx.x * 128;
    const int arow = tid >> 1;            // 0..127
    const int acol = (tid & 1) << 2;      // 0 or 4
    const int brow = tid >> 5;            // 0..7
    const int bcol = (tid & 31) << 2;     // 0..124
    const int ty   = tid >> 4;            // 0..15
    const int tx   = tid & 15;            // 0..15

    float acc[8][8];
#pragma unroll
    for (int i = 0; i < 8; i++)
#pragma unroll
        for (int j = 0; j < 8; j++) acc[i][j] = 0.f;

    const float* Ap = A + (size_t)(bm + arow) * K + acol;
    const float* Bp = B + (size_t)brow * N + bn + bcol;

    for (int k0 = 0; k0 < K; k0 += 8) {
        float4 av = *(const float4*)(Ap + k0);
        As[acol + 0][arow] = av.x;
        As[acol + 1][arow] = av.y;
        As[acol + 2][arow] = av.z;
        As[acol + 3][arow] = av.w;
        *(float4*)&Bs[brow][bcol] = *(const float4*)(Bp + (size_t)k0 * N);
        __syncthreads();

#pragma unroll
        for (int kk = 0; kk < 8; kk++) {
            float a[8], b[8];
            *(float4*)(a)     = *(const float4*)&As[kk][ty * 4];
            *(float4*)(a + 4) = *(const float4*)&As[kk][64 + ty * 4];
            *(float4*)(b)     = *(const float4*)&Bs[kk][tx * 4];
            *(float4*)(b + 4) = *(const float4*)&Bs[kk][64 + tx * 4];
#pragma unroll
            for (int i = 0; i < 8; i++)
#pragma unroll
                for (int j = 0; j < 8; j++)
                    acc[i][j] = fmaf(a[i], b[j], acc[i][j]);
        }
        __syncthreads();
    }

#pragma unroll
    for (int i = 0; i < 8; i++) {
        int r = bm + ((i < 4) ? (ty * 4 + i) : (64 + ty * 4 + i - 4));
#pragma unroll
        for (int jh = 0; jh < 2; jh++) {
            int c = bn + jh * 64 + tx * 4;
            float4 o;
            o.x = acc[i][jh * 4 + 0] + bias[c + 0];
            o.y = acc[i][jh * 4 + 1] + bias[c + 1];
            o.z = acc[i][jh * 4 + 2] + bias[c + 2];
            o.w = acc[i][jh * 4 + 3] + bias[c + 3];
            *(float4*)(C + (size_t)r * N + c) = o;
        }
    }
}

// ---------------------------------------------------------------------------
// Flash-style attention. One CTA = (batch b, head h, 64 query rows).
// Streams 64-wide KV tiles with online softmax. K is stored d-major (stride
// 68 to soften transpose-store conflicts) so both QK^T and PV smem reads are
// contiguous float4.
// Smem (floats): Qs[64*64] Kt[64*68] Vs[64*64] Ps[64*64] = 16640 -> 66560 B.
// ---------------------------------------------------------------------------
__global__ __launch_bounds__(256) void attn_kernel(
    const float* __restrict__ qkv, const float* __restrict__ mask,
    float* __restrict__ out)
{
    extern __shared__ float sm[];
    float* Qs = sm;                    // [64][64]
    float* Kt = sm + 4096;             // [64][68]  (d-major)
    float* Vs = sm + 4096 + 4352;      // [64][64]
    float* Ps = Vs + 4096;             // [64][64]

    const int qt  = blockIdx.x * 64;
    const int h   = blockIdx.y;
    const int b   = blockIdx.z;
    const int tid = threadIdx.x;
    const int ty  = tid >> 4, tx = tid & 15;
    const int r0  = ty * 4;            // this thread's S/O row base
    const int c0  = tx * 4;            // this thread's S col / O col base

    // load Q tile (coalesced float4)
#pragma unroll
    for (int i = 0; i < 4; i++) {
        int idx = tid + i * 256;               // 0..1023
        int r = idx >> 4, c = (idx & 15) << 2;
        const float* p = qkv + ((size_t)(b * T_SEQ + qt + r)) * 3072 + h * 64 + c;
        *(float4*)&Qs[r * 64 + c] = *(const float4*)p;
    }

    float m_i[4], l_i[4], O[4][4];
#pragma unroll
    for (int i = 0; i < 4; i++) {
        m_i[i] = -1e30f; l_i[i] = 0.f;
        O[i][0] = O[i][1] = O[i][2] = O[i][3] = 0.f;
    }
    const float* mb = mask + (size_t)b * T_SEQ;

    for (int kt = 0; kt < T_SEQ; kt += 64) {
        __syncthreads();    // previous tile's Ps/Vs reads done (also covers Q load)
        // load K (transposed into d-major) and V
#pragma unroll
        for (int i = 0; i < 4; i++) {
            int idx = tid + i * 256;
            int r = idx >> 4, c = (idx & 15) << 2;
            const float* base = qkv + ((size_t)(b * T_SEQ + kt + r)) * 3072 + h * 64;
            float4 kv = *(const float4*)(base + 1024 + c);
            Kt[(c + 0) * 68 + r] = kv.x;
            Kt[(c + 1) * 68 + r] = kv.y;
            Kt[(c + 2) * 68 + r] = kv.z;
            Kt[(c + 3) * 68 + r] = kv.w;
            *(float4*)&Vs[r * 64 + c] = *(const float4*)(base + 2048 + c);
        }
        __syncthreads();

        // S = Q @ K^T  (4x4 per thread)
        float S[4][4] = {{0.f, 0.f, 0.f, 0.f}, {0.f, 0.f, 0.f, 0.f},
                         {0.f, 0.f, 0.f, 0.f}, {0.f, 0.f, 0.f, 0.f}};
#pragma unroll
        for (int d4 = 0; d4 < 64; d4 += 4) {
            float qa[4][4];
#pragma unroll
            for (int i = 0; i < 4; i++)
                *(float4*)qa[i] = *(const float4*)&Qs[(r0 + i) * 64 + d4];
#pragma unroll
            for (int dd = 0; dd < 4; dd++) {
                float4 kk = *(const float4*)&Kt[(d4 + dd) * 68 + c0];
#pragma unroll
                for (int i = 0; i < 4; i++) {
                    S[i][0] = fmaf(qa[i][dd], kk.x, S[i][0]);
                    S[i][1] = fmaf(qa[i][dd], kk.y, S[i][1]);
                    S[i][2] = fmaf(qa[i][dd], kk.z, S[i][2]);
                    S[i][3] = fmaf(qa[i][dd], kk.w, S[i][3]);
                }
            }
        }

        // scale + double mask, online softmax (rows reduced across 16 tx lanes)
        float mk[4];
#pragma unroll
        for (int j = 0; j < 4; j++) mk[j] = 2.f * mb[kt + c0 + j];

#pragma unroll
        for (int i = 0; i < 4; i++) {
#pragma unroll
            for (int j = 0; j < 4; j++) S[i][j] = fmaf(S[i][j], 0.125f, mk[j]);
            float mx = fmaxf(fmaxf(S[i][0], S[i][1]), fmaxf(S[i][2], S[i][3]));
#pragma unroll
            for (int off = 8; off >= 1; off >>= 1)
                mx = fmaxf(mx, __shfl_xor_sync(0xffffffffu, mx, off, 16));
            float mnew = fmaxf(m_i[i], mx);
            float corr = __expf(m_i[i] - mnew);
            m_i[i] = mnew;
            float rs = 0.f;
#pragma unroll
            for (int j = 0; j < 4; j++) { S[i][j] = __expf(S[i][j] - mnew); rs += S[i][j]; }
#pragma unroll
            for (int off = 8; off >= 1; off >>= 1)
                rs += __shfl_xor_sync(0xffffffffu, rs, off, 16);
            l_i[i] = l_i[i] * corr + rs;
#pragma unroll
            for (int j = 0; j < 4; j++) O[i][j] *= corr;
            *(float4*)&Ps[(r0 + i) * 64 + c0] =
                make_float4(S[i][0], S[i][1], S[i][2], S[i][3]);
        }
        __syncthreads();

        // O += P @ V
#pragma unroll
        for (int k4 = 0; k4 < 64; k4 += 4) {
            float pa[4][4];
#pragma unroll
            for (int i = 0; i < 4; i++)
                *(float4*)pa[i] = *(const float4*)&Ps[(r0 + i) * 64 + k4];
#pragma unroll
            for (int kk = 0; kk < 4; kk++) {
                float4 vv = *(const float4*)&Vs[(k4 + kk) * 64 + c0];
#pragma unroll
                for (int i = 0; i < 4; i++) {
                    O[i][0] = fmaf(pa[i][kk], vv.x, O[i][0]);
                    O[i][1] = fmaf(pa[i][kk], vv.y, O[i][1]);
                    O[i][2] = fmaf(pa[i][kk], vv.z, O[i][2]);
                    O[i][3] = fmaf(pa[i][kk], vv.w, O[i][3]);
                }
            }
        }
    }

    // epilogue: normalize and store attn_out[B,T,H,hd] (== [B,T,D])
#pragma unroll
    for (int i = 0; i < 4; i++) {
        float inv = 1.f / l_i[i];
        float4 o = make_float4(O[i][0] * inv, O[i][1] * inv, O[i][2] * inv, O[i][3] * inv);
        *(float4*)(out + ((size_t)(b * T_SEQ + qt + r0 + i)) * D_MODEL + h * 64 + c0) = o;
    }
}

// ---------------------------------------------------------------------------
extern "C" void kernel_launch(void* const* d_in, const int* in_sizes, int n_in,
                              void* d_out, int out_size)
{
    const float* x      = (const float*)d_in[0];
    const float* mask   = (const float*)d_in[1];
    const float* w_attn = (const float*)d_in[2];
    const float* b_attn = (const float*)d_in[3];
    const float* w_proj = (const float*)d_in[4];
    const float* b_proj = (const float*)d_in[5];
    float* out = (float*)d_out;

    float *qkv_s = nullptr, *att_s = nullptr;
    cudaGetSymbolAddress((void**)&qkv_s, g_qkv);
    cudaGetSymbolAddress((void**)&att_s, g_att);

    const int smem_attn = 66560;  // (4096 + 4352 + 4096 + 4096) * 4
    cudaFuncSetAttribute(attn_kernel,
                         cudaFuncAttributeMaxDynamicSharedMemorySize, smem_attn);

    // 1) qkv = x @ w_attn + b_attn        [4096, 3072]
    sgemm_bias<<<dim3(3072 / 128, BT_ROWS / 128), 256>>>(
        x, w_attn, b_attn, qkv_s, BT_ROWS, 3072, D_MODEL);

    // 2) attention -> g_att               [4096, 1024]
    attn_kernel<<<dim3(T_SEQ / 64, 16, 2), 256, smem_attn>>>(qkv_s, mask, att_s);

    // 3) out = att @ w_proj + b_proj      [4096, 1024]
    sgemm_bias<<<dim3(D_MODEL / 128, BT_ROWS / 128), 256>>>(
        att_s, w_proj, b_proj, out, BT_ROWS, D_MODEL, D_MODEL);
}

// round 3
// speedup vs baseline: 1.3300x; 1.3300x over previous
#include <cuda_runtime.h>
#include <cuda_bf16.h>
#include <cstdint>

#define T_SEQ 2048
#define D_MODEL 1024
#define BT_ROWS 4096            // B*T

// ---------------------------------------------------------------------------
// Scratch (device globals; no allocations anywhere)
// ---------------------------------------------------------------------------
__device__ float g_qkv[(size_t)BT_ROWS * 3072];        // 50 MB
__device__ float g_att[(size_t)BT_ROWS * 1024];        // 16 MB
__device__ __nv_bfloat16 g_xa_hi[(size_t)BT_ROWS * 1024];
__device__ __nv_bfloat16 g_xa_lo[(size_t)BT_ROWS * 1024];
__device__ __nv_bfloat16 g_wa_hi[(size_t)3072 * 1024];  // w_attn^T [N,K]
__device__ __nv_bfloat16 g_wa_lo[(size_t)3072 * 1024];
__device__ __nv_bfloat16 g_wp_hi[(size_t)1024 * 1024];  // w_proj^T [N,K]
__device__ __nv_bfloat16 g_wp_lo[(size_t)1024 * 1024];
__device__ __nv_bfloat16 g_at_hi[(size_t)BT_ROWS * 1024];
__device__ __nv_bfloat16 g_at_lo[(size_t)BT_ROWS * 1024];

// ---------------------------------------------------------------------------
// Helpers (all plain sm_80-era PTX: cp.async, ldmatrix, mma.sync — no 'a' features)
// ---------------------------------------------------------------------------
__device__ __forceinline__ uint32_t smem_u32(const void* p) {
    uint32_t a;
    asm("{ .reg .u64 t; cvta.to.shared.u64 t, %1; cvt.u32.u64 %0, t; }"
        : "=r"(a) : "l"(p));
    return a;
}

__device__ __forceinline__ void cpa16(uint32_t s, const void* g) {
    asm volatile("cp.async.cg.shared.global [%0], [%1], 16;" :: "r"(s), "l"(g));
}

__device__ __forceinline__ void ldsm4(uint32_t* r, uint32_t a) {
    asm volatile("ldmatrix.sync.aligned.m8n8.x4.shared.b16 {%0,%1,%2,%3}, [%4];"
                 : "=r"(r[0]), "=r"(r[1]), "=r"(r[2]), "=r"(r[3]) : "r"(a));
}

__device__ __forceinline__ void mma16816(float* d, const uint32_t* a,
                                         const uint32_t* b) {
    asm volatile(
        "mma.sync.aligned.m16n8k16.row.col.f32.bf16.bf16.f32 "
        "{%0,%1,%2,%3}, {%4,%5,%6,%7}, {%8,%9}, {%0,%1,%2,%3};"
        : "+f"(d[0]), "+f"(d[1]), "+f"(d[2]), "+f"(d[3])
        : "r"(a[0]), "r"(a[1]), "r"(a[2]), "r"(a[3]), "r"(b[0]), "r"(b[1]));
}

// ---------------------------------------------------------------------------
// Split kernels: fp32 -> bf16 hi + bf16 lo (lo = bf16(x - float(hi)))
// ---------------------------------------------------------------------------
__global__ void split_mat(const float* __restrict__ in,
                          __nv_bfloat16* __restrict__ hi,
                          __nv_bfloat16* __restrict__ lo, int n) {
    int i = (blockIdx.x * blockDim.x + threadIdx.x) * 4;
    if (i >= n) return;
    float4 v = *(const float4*)(in + i);
    float vv[4] = {v.x, v.y, v.z, v.w};
    __nv_bfloat162 h0, h1, l0, l1;
    __nv_bfloat16 h[4], l[4];
#pragma unroll
    for (int j = 0; j < 4; j++) {
        h[j] = __float2bfloat16(vv[j]);
        l[j] = __float2bfloat16(vv[j] - __bfloat162float(h[j]));
    }
    h0.x = h[0]; h0.y = h[1]; h1.x = h[2]; h1.y = h[3];
    l0.x = l[0]; l0.y = l[1]; l1.x = l[2]; l1.y = l[3];
    ((__nv_bfloat162*)(hi + i))[0] = h0;
    ((__nv_bfloat162*)(hi + i))[1] = h1;
    ((__nv_bfloat162*)(lo + i))[0] = l0;
    ((__nv_bfloat162*)(lo + i))[1] = l1;
}

// w:[Kd,Nd] row-major -> out hi/lo:[Nd,Kd] (transposed), split to bf16 hi/lo
__global__ void split_wT(const float* __restrict__ w,
                         __nv_bfloat16* __restrict__ hi,
                         __nv_bfloat16* __restrict__ lo, int Kd, int Nd) {
    __shared__ float t[32][33];
    int k0 = blockIdx.y * 32, n0 = blockIdx.x * 32;
    int tx = threadIdx.x, ty = threadIdx.y;   // block (32,8)
#pragma unroll
    for (int j = 0; j < 32; j += 8)
        t[ty + j][tx] = w[(size_t)(k0 + ty + j) * Nd + n0 + tx];
    __syncthreads();
#pragma unroll
    for (int j = 0; j < 32; j += 8) {
        float v = t[tx][ty + j];
        __nv_bfloat16 h = __float2bfloat16(v);
        size_t o = (size_t)(n0 + ty + j) * Kd + k0 + tx;
        hi[o] = h;
        lo[o] = __float2bfloat16(v - __bfloat162float(h));
    }
}

// ---------------------------------------------------------------------------
// HMMA bf16-split GEMM: C[M,N] = A[M,K] @ B^T[N,K] + bias
//   A hi/lo bf16 [M,K]; B hi/lo bf16 [N,K] (pre-transposed).
//   128x128 CTA tile, 4 warps of 64x64, BK=32, 2-stage cp.async pipeline.
//   D = Ah*Bh + Ah*Bl + Al*Bh (fp32 accum in registers).
// Smem: per stage 4 tiles (Ah,Al,Bh,Bl) of 128 rows x 80B (padded; conflict-
// free ldmatrix: bank stride 20) = 40960 B; x2 stages = 81920 B.
// ---------------------------------------------------------------------------
#define GBK 32
#define ROWB 80
#define TILE_B (128 * ROWB)          // 10240
#define STAGE_B (4 * TILE_B)         // 40960
#define GEMM_SMEM (2 * STAGE_B)      // 81920

__global__ __launch_bounds__(128) void gemm_hmma(
    const __nv_bfloat16* __restrict__ Ahi, const __nv_bfloat16* __restrict__ Alo,
    const __nv_bfloat16* __restrict__ Bhi, const __nv_bfloat16* __restrict__ Blo,
    const float* __restrict__ bias, float* __restrict__ C, int N, int K)
{
    extern __shared__ char smc[];
    const uint32_t sb = smem_u32(smc);
    const int tid = threadIdx.x, lane = tid & 31, wid = tid >> 5;
    const int bm = blockIdx.y * 128, bn = blockIdx.x * 128;
    const int mbw = (wid & 1) * 64;      // warp m-offset in tile
    const int nbw = (wid >> 1) * 64;     // warp n-offset in tile

    float acc[4][8][4];
#pragma unroll
    for (int m = 0; m < 4; m++)
#pragma unroll
        for (int n = 0; n < 8; n++)
#pragma unroll
            for (int j = 0; j < 4; j++) acc[m][n][j] = 0.f;

    // ldmatrix per-thread base offsets (quad = lane>>3, t = lane&7)
    // A frag (16m x 16k): rows (quad&1)*8 + t, kbytes (quad>>1)*16
    const uint32_t aoff =
        (uint32_t)(mbw + ((lane >> 3) & 1) * 8 + (lane & 7)) * ROWB +
        (uint32_t)(lane >> 4) * 16;
    // B frag pair (16n x 16k): rows (quad>>1)*8 + t, kbytes (quad&1)*16
    const uint32_t boff =
        (uint32_t)(nbw + (lane >> 4) * 8 + (lane & 7)) * ROWB +
        (uint32_t)((lane >> 3) & 1) * 16;

    auto load_stage = [&](int s, int kt) {
        const uint32_t st = sb + s * STAGE_B;
        const int kc = kt * GBK;
        const __nv_bfloat16* gp[4] = {Ahi, Alo, Bhi, Blo};
#pragma unroll
        for (int tile = 0; tile < 4; tile++) {
            const int rbase = (tile < 2) ? bm : bn;
            const uint32_t td = st + tile * TILE_B;
#pragma unroll
            for (int i = 0; i < 2; i++) {
                int p = tid + i * 128;           // 0..255 (row, half)
                int row = p >> 1, hf = p & 1;
                const __nv_bfloat16* g =
                    gp[tile] + (size_t)(rbase + row) * K + kc + hf * 16;
                uint32_t sd = td + row * ROWB + hf * 32;
                cpa16(sd, g);
                cpa16(sd + 16, g + 8);
            }
        }
        asm volatile("cp.async.commit_group;" ::: "memory");
    };

    const int KT = K / GBK;
    load_stage(0, 0);
    load_stage(1, 1);

    for (int kt = 0; kt < KT; kt++) {
        const int s = kt & 1;
        asm volatile("cp.async.wait_group 1;" ::: "memory");
        __syncthreads();

        const uint32_t st = sb + s * STAGE_B;
        const uint32_t stAh = st, stAl = st + TILE_B;
        const uint32_t stBh = st + 2 * TILE_B, stBl = st + 3 * TILE_B;

#pragma unroll
        for (int ks = 0; ks < 2; ks++) {
            const uint32_t ko = ks * 32;       // 16 k-elems = 32 bytes
            uint32_t bh[4][4], bl[4][4], af[4][4];
#pragma unroll
            for (int p = 0; p < 4; p++)
                ldsm4(bh[p], stBh + boff + p * 16 * ROWB + ko);
#pragma unroll
            for (int m = 0; m < 4; m++)
                ldsm4(af[m], stAh + aoff + m * 16 * ROWB + ko);
            // term 1: Ah * Bh
#pragma unroll
            for (int n = 0; n < 8; n++)
#pragma unroll
                for (int m = 0; m < 4; m++)
                    mma16816(acc[m][n], af[m], &bh[n >> 1][(n & 1) * 2]);
#pragma unroll
            for (int p = 0; p < 4; p++)
                ldsm4(bl[p], stBl + boff + p * 16 * ROWB + ko);
            // term 2: Ah * Bl
#pragma unroll
            for (int n = 0; n < 8; n++)
#pragma unroll
                for (int m = 0; m < 4; m++)
                    mma16816(acc[m][n], af[m], &bl[n >> 1][(n & 1) * 2]);
            // term 3: Al * Bh (reuse af regs)
#pragma unroll
            for (int m = 0; m < 4; m++)
                ldsm4(af[m], stAl + aoff + m * 16 * ROWB + ko);
#pragma unroll
            for (int n = 0; n < 8; n++)
#pragma unroll
                for (int m = 0; m < 4; m++)
                    mma16816(acc[m][n], af[m], &bh[n >> 1][(n & 1) * 2]);
        }
        __syncthreads();
        if (kt + 2 < KT) load_stage(s, kt + 2);
    }

    // Epilogue: fragment layout -> global, fused bias
    const int rql = lane >> 2, cql = (lane & 3) * 2;
#pragma unroll
    for (int m = 0; m < 4; m++) {
        const int row = bm + mbw + m * 16 + rql;
#pragma unroll
        for (int n = 0; n < 8; n++) {
            const int col = bn + nbw + n * 8 + cql;
            const float bx = bias[col], by = bias[col + 1];
            float2 o0 = make_float2(acc[m][n][0] + bx, acc[m][n][1] + by);
            float2 o1 = make_float2(acc[m][n][2] + bx, acc[m][n][3] + by);
            *(float2*)(C + (size_t)row * N + col) = o0;
            *(float2*)(C + (size_t)(row + 8) * N + col) = o1;
        }
    }
}

// ---------------------------------------------------------------------------
// Flash-style fp32 attention (unchanged; HMMA conversion is next round)
// ---------------------------------------------------------------------------
__global__ __launch_bounds__(256) void attn_kernel(
    const float* __restrict__ qkv, const float* __restrict__ mask,
    float* __restrict__ out)
{
    extern __shared__ float sm[];
    float* Qs = sm;                    // [64][64]
    float* Kt = sm + 4096;             // [64][68]  (d-major)
    float* Vs = sm + 4096 + 4352;      // [64][64]
    float* Ps = Vs + 4096;             // [64][64]

    const int qt  = blockIdx.x * 64;
    const int h   = blockIdx.y;
    const int b   = blockIdx.z;
    const int tid = threadIdx.x;
    const int ty  = tid >> 4, tx = tid & 15;
    const int r0  = ty * 4;
    const int c0  = tx * 4;

#pragma unroll
    for (int i = 0; i < 4; i++) {
        int idx = tid + i * 256;
        int r = idx >> 4, c = (idx & 15) << 2;
        const float* p = qkv + ((size_t)(b * T_SEQ + qt + r)) * 3072 + h * 64 + c;
        *(float4*)&Qs[r * 64 + c] = *(const float4*)p;
    }

    float m_i[4], l_i[4], O[4][4];
#pragma unroll
    for (int i = 0; i < 4; i++) {
        m_i[i] = -1e30f; l_i[i] = 0.f;
        O[i][0] = O[i][1] = O[i][2] = O[i][3] = 0.f;
    }
    const float* mb = mask + (size_t)b * T_SEQ;

    for (int kt = 0; kt < T_SEQ; kt += 64) {
        __syncthreads();
#pragma unroll
        for (int i = 0; i < 4; i++) {
            int idx = tid + i * 256;
            int r = idx >> 4, c = (idx & 15) << 2;
            const float* base = qkv + ((size_t)(b * T_SEQ + kt + r)) * 3072 + h * 64;
            float4 kv = *(const float4*)(base + 1024 + c);
            Kt[(c + 0) * 68 + r] = kv.x;
            Kt[(c + 1) * 68 + r] = kv.y;
            Kt[(c + 2) * 68 + r] = kv.z;
            Kt[(c + 3) * 68 + r] = kv.w;
            *(float4*)&Vs[r * 64 + c] = *(const float4*)(base + 2048 + c);
        }
        __syncthreads();

        float S[4][4] = {{0.f,0.f,0.f,0.f},{0.f,0.f,0.f,0.f},
                         {0.f,0.f,0.f,0.f},{0.f,0.f,0.f,0.f}};
#pragma unroll
        for (int d4 = 0; d4 < 64; d4 += 4) {
            float qa[4][4];
#pragma unroll
            for (int i = 0; i < 4; i++)
                *(float4*)qa[i] = *(const float4*)&Qs[(r0 + i) * 64 + d4];
#pragma unroll
            for (int dd = 0; dd < 4; dd++) {
                float4 kk = *(const float4*)&Kt[(d4 + dd) * 68 + c0];
#pragma unroll
                for (int i = 0; i < 4; i++) {
                    S[i][0] = fmaf(qa[i][dd], kk.x, S[i][0]);
                    S[i][1] = fmaf(qa[i][dd], kk.y, S[i][1]);
                    S[i][2] = fmaf(qa[i][dd], kk.z, S[i][2]);
                    S[i][3] = fmaf(qa[i][dd], kk.w, S[i][3]);
                }
            }
        }

        float mk[4];
#pragma unroll
        for (int j = 0; j < 4; j++) mk[j] = 2.f * mb[kt + c0 + j];

#pragma unroll
        for (int i = 0; i < 4; i++) {
#pragma unroll
            for (int j = 0; j < 4; j++) S[i][j] = fmaf(S[i][j], 0.125f, mk[j]);
            float mx = fmaxf(fmaxf(S[i][0], S[i][1]), fmaxf(S[i][2], S[i][3]));
#pragma unroll
            for (int off = 8; off >= 1; off >>= 1)
                mx = fmaxf(mx, __shfl_xor_sync(0xffffffffu, mx, off, 16));
            float mnew = fmaxf(m_i[i], mx);
            float corr = __expf(m_i[i] - mnew);
            m_i[i] = mnew;
            float rs = 0.f;
#pragma unroll
            for (int j = 0; j < 4; j++) { S[i][j] = __expf(S[i][j] - mnew); rs += S[i][j]; }
#pragma unroll
            for (int off = 8; off >= 1; off >>= 1)
                rs += __shfl_xor_sync(0xffffffffu, rs, off, 16);
            l_i[i] = l_i[i] * corr + rs;
#pragma unroll
            for (int j = 0; j < 4; j++) O[i][j] *= corr;
            *(float4*)&Ps[(r0 + i) * 64 + c0] =
                make_float4(S[i][0], S[i][1], S[i][2], S[i][3]);
        }
        __syncthreads();

#pragma unroll
        for (int k4 = 0; k4 < 64; k4 += 4) {
            float pa[4][4];
#pragma unroll
            for (int i = 0; i < 4; i++)
                *(float4*)pa[i] = *(const float4*)&Ps[(r0 + i) * 64 + k4];
#pragma unroll
            for (int kk = 0; kk < 4; kk++) {
                float4 vv = *(const float4*)&Vs[(k4 + kk) * 64 + c0];
#pragma unroll
                for (int i = 0; i < 4; i++) {
                    O[i][0] = fmaf(pa[i][kk], vv.x, O[i][0]);
                    O[i][1] = fmaf(pa[i][kk], vv.y, O[i][1]);
                    O[i][2] = fmaf(pa[i][kk], vv.z, O[i][2]);
                    O[i][3] = fmaf(pa[i][kk], vv.w, O[i][3]);
                }
            }
        }
    }

#pragma unroll
    for (int i = 0; i < 4; i++) {
        float inv = 1.f / l_i[i];
        float4 o = make_float4(O[i][0] * inv, O[i][1] * inv, O[i][2] * inv, O[i][3] * inv);
        *(float4*)(out + ((size_t)(b * T_SEQ + qt + r0 + i)) * D_MODEL + h * 64 + c0) = o;
    }
}

// ---------------------------------------------------------------------------
extern "C" void kernel_launch(void* const* d_in, const int* in_sizes, int n_in,
                              void* d_out, int out_size)
{
    const float* x      = (const float*)d_in[0];
    const float* mask   = (const float*)d_in[1];
    const float* w_attn = (const float*)d_in[2];
    const float* b_attn = (const float*)d_in[3];
    const float* w_proj = (const float*)d_in[4];
    const float* b_proj = (const float*)d_in[5];
    float* out = (float*)d_out;

    float *qkv_s, *att_s;
    __nv_bfloat16 *xa_hi, *xa_lo, *wa_hi, *wa_lo, *wp_hi, *wp_lo, *at_hi, *at_lo;
    cudaGetSymbolAddress((void**)&qkv_s, g_qkv);
    cudaGetSymbolAddress((void**)&att_s, g_att);
    cudaGetSymbolAddress((void**)&xa_hi, g_xa_hi);
    cudaGetSymbolAddress((void**)&xa_lo, g_xa_lo);
    cudaGetSymbolAddress((void**)&wa_hi, g_wa_hi);
    cudaGetSymbolAddress((void**)&wa_lo, g_wa_lo);
    cudaGetSymbolAddress((void**)&wp_hi, g_wp_hi);
    cudaGetSymbolAddress((void**)&wp_lo, g_wp_lo);
    cudaGetSymbolAddress((void**)&at_hi, g_at_hi);
    cudaGetSymbolAddress((void**)&at_lo, g_at_lo);

    const int smem_attn = 66560;
    cudaFuncSetAttribute(attn_kernel,
                         cudaFuncAttributeMaxDynamicSharedMemorySize, smem_attn);
    cudaFuncSetAttribute(gemm_hmma,
                         cudaFuncAttributeMaxDynamicSharedMemorySize, GEMM_SMEM);

    const int nx = BT_ROWS * 1024;

    // 1) splits
    split_mat<<<nx / 4 / 256, 256>>>(x, xa_hi, xa_lo, nx);
    split_wT<<<dim3(3072 / 32, 1024 / 32), dim3(32, 8)>>>(w_attn, wa_hi, wa_lo, 1024, 3072);
    split_wT<<<dim3(1024 / 32, 1024 / 32), dim3(32, 8)>>>(w_proj, wp_hi, wp_lo, 1024, 1024);

    // 2) qkv = x @ w_attn + b_attn   [4096, 3072]  (HMMA)
    gemm_hmma<<<dim3(3072 / 128, BT_ROWS / 128), 128, GEMM_SMEM>>>(
        xa_hi, xa_lo, wa_hi, wa_lo, b_attn, qkv_s, 3072, 1024);

    // 3) attention (fp32)
    attn_kernel<<<dim3(T_SEQ / 64, 16, 2), 256, smem_attn>>>(qkv_s, mask, att_s);

    // 4) split attention output, then proj (HMMA)
    split_mat<<<nx / 4 / 256, 256>>>(att_s, at_hi, at_lo, nx);
    gemm_hmma<<<dim3(1024 / 128, BT_ROWS / 128), 128, GEMM_SMEM>>>(
        at_hi, at_lo, wp_hi, wp_lo, b_proj, out, 1024, 1024);
}

// round 4
// speedup vs baseline: 2.4947x; 1.8757x over previous
#include <cuda_runtime.h>
#include <cuda_bf16.h>
#include <cstdint>

#define T_SEQ 2048
#define D_MODEL 1024
#define BT_ROWS 4096            // B*T

// ---------------------------------------------------------------------------
// Scratch (device globals; no allocations anywhere)
// ---------------------------------------------------------------------------
__device__ __nv_bfloat16 g_qkv_hi[(size_t)BT_ROWS * 3072];
__device__ __nv_bfloat16 g_qkv_lo[(size_t)BT_ROWS * 3072];
__device__ __nv_bfloat16 g_att_hi[(size_t)BT_ROWS * 1024];
__device__ __nv_bfloat16 g_att_lo[(size_t)BT_ROWS * 1024];
__device__ __nv_bfloat16 g_xa_hi[(size_t)BT_ROWS * 1024];
__device__ __nv_bfloat16 g_xa_lo[(size_t)BT_ROWS * 1024];
__device__ __nv_bfloat16 g_wa_hi[(size_t)3072 * 1024];  // w_attn^T [N,K]
__device__ __nv_bfloat16 g_wa_lo[(size_t)3072 * 1024];
__device__ __nv_bfloat16 g_wp_hi[(size_t)1024 * 1024];  // w_proj^T [N,K]
__device__ __nv_bfloat16 g_wp_lo[(size_t)1024 * 1024];

// ---------------------------------------------------------------------------
// Helpers (plain sm_80-era PTX only — harness compiles for sm_103 without 'a')
// ---------------------------------------------------------------------------
__device__ __forceinline__ uint32_t smem_u32(const void* p) {
    uint32_t a;
    asm("{ .reg .u64 t; cvta.to.shared.u64 t, %1; cvt.u32.u64 %0, t; }"
        : "=r"(a) : "l"(p));
    return a;
}

__device__ __forceinline__ void cpa16(uint32_t s, const void* g) {
    asm volatile("cp.async.cg.shared.global [%0], [%1], 16;" :: "r"(s), "l"(g));
}

__device__ __forceinline__ void ldsm4(uint32_t* r, uint32_t a) {
    asm volatile("ldmatrix.sync.aligned.m8n8.x4.shared.b16 {%0,%1,%2,%3}, [%4];"
                 : "=r"(r[0]), "=r"(r[1]), "=r"(r[2]), "=r"(r[3]) : "r"(a));
}

__device__ __forceinline__ void ldsm4t(uint32_t* r, uint32_t a) {
    asm volatile("ldmatrix.sync.aligned.m8n8.x4.trans.shared.b16 {%0,%1,%2,%3}, [%4];"
                 : "=r"(r[0]), "=r"(r[1]), "=r"(r[2]), "=r"(r[3]) : "r"(a));
}

__device__ __forceinline__ void mma16816(float* d, const uint32_t* a,
                                         const uint32_t* b) {
    asm volatile(
        "mma.sync.aligned.m16n8k16.row.col.f32.bf16.bf16.f32 "
        "{%0,%1,%2,%3}, {%4,%5,%6,%7}, {%8,%9}, {%0,%1,%2,%3};"
        : "+f"(d[0]), "+f"(d[1]), "+f"(d[2]), "+f"(d[3])
        : "r"(a[0]), "r"(a[1]), "r"(a[2]), "r"(a[3]), "r"(b[0]), "r"(b[1]));
}

// split a pair of fp32 into packed bf16x2 hi and lo
__device__ __forceinline__ void split2(float a, float b, uint32_t& hi, uint32_t& lo) {
    __nv_bfloat162 h, l;
    h.x = __float2bfloat16(a);
    h.y = __float2bfloat16(b);
    l.x = __float2bfloat16(a - __bfloat162float(h.x));
    l.y = __float2bfloat16(b - __bfloat162float(h.y));
    hi = *(uint32_t*)&h;
    lo = *(uint32_t*)&l;
}

// ---------------------------------------------------------------------------
// Split kernels: fp32 -> bf16 hi + bf16 lo
// ---------------------------------------------------------------------------
__global__ void split_mat(const float* __restrict__ in,
                          __nv_bfloat16* __restrict__ hi,
                          __nv_bfloat16* __restrict__ lo, int n) {
    int i = (blockIdx.x * blockDim.x + threadIdx.x) * 4;
    if (i >= n) return;
    float4 v = *(const float4*)(in + i);
    uint32_t h0, h1, l0, l1;
    split2(v.x, v.y, h0, l0);
    split2(v.z, v.w, h1, l1);
    ((uint32_t*)(hi + i))[0] = h0;
    ((uint32_t*)(hi + i))[1] = h1;
    ((uint32_t*)(lo + i))[0] = l0;
    ((uint32_t*)(lo + i))[1] = l1;
}

// w:[Kd,Nd] row-major -> out hi/lo:[Nd,Kd] (transposed), split to bf16
__global__ void split_wT(const float* __restrict__ w,
                         __nv_bfloat16* __restrict__ hi,
                         __nv_bfloat16* __restrict__ lo, int Kd, int Nd) {
    __shared__ float t[32][33];
    int k0 = blockIdx.y * 32, n0 = blockIdx.x * 32;
    int tx = threadIdx.x, ty = threadIdx.y;   // block (32,8)
#pragma unroll
    for (int j = 0; j < 32; j += 8)
        t[ty + j][tx] = w[(size_t)(k0 + ty + j) * Nd + n0 + tx];
    __syncthreads();
#pragma unroll
    for (int j = 0; j < 32; j += 8) {
        float v = t[tx][ty + j];
        __nv_bfloat16 h = __float2bfloat16(v);
        size_t o = (size_t)(n0 + ty + j) * Kd + k0 + tx;
        hi[o] = h;
        lo[o] = __float2bfloat16(v - __bfloat162float(h));
    }
}

// ---------------------------------------------------------------------------
// HMMA bf16-split GEMM: C[M,N] = A[M,K] @ B^T[N,K] + bias
// SPLIT_OUT=0: write fp32 C.  SPLIT_OUT=1: write bf16 hi/lo (fused split).
// ---------------------------------------------------------------------------
#define GBK 32
#define ROWB 80
#define TILE_B (128 * ROWB)
#define STAGE_B (4 * TILE_B)
#define GEMM_SMEM (2 * STAGE_B)

template <int SPLIT_OUT>
__global__ __launch_bounds__(128) void gemm_hmma(
    const __nv_bfloat16* __restrict__ Ahi, const __nv_bfloat16* __restrict__ Alo,
    const __nv_bfloat16* __restrict__ Bhi, const __nv_bfloat16* __restrict__ Blo,
    const float* __restrict__ bias, float* __restrict__ C,
    __nv_bfloat16* __restrict__ Chi, __nv_bfloat16* __restrict__ Clo,
    int N, int K)
{
    extern __shared__ char smc[];
    const uint32_t sb = smem_u32(smc);
    const int tid = threadIdx.x, lane = tid & 31, wid = tid >> 5;
    const int bm = blockIdx.y * 128, bn = blockIdx.x * 128;
    const int mbw = (wid & 1) * 64;
    const int nbw = (wid >> 1) * 64;

    float acc[4][8][4];
#pragma unroll
    for (int m = 0; m < 4; m++)
#pragma unroll
        for (int n = 0; n < 8; n++)
#pragma unroll
            for (int j = 0; j < 4; j++) acc[m][n][j] = 0.f;

    const uint32_t aoff =
        (uint32_t)(mbw + (lane & 15)) * ROWB + (uint32_t)(lane >> 4) * 16;
    const uint32_t boff =
        (uint32_t)(nbw + (lane >> 4) * 8 + (lane & 7)) * ROWB +
        (uint32_t)((lane >> 3) & 1) * 16;

    auto load_stage = [&](int s, int kt) {
        const uint32_t st = sb + s * STAGE_B;
        const int kc = kt * GBK;
        const __nv_bfloat16* gp[4] = {Ahi, Alo, Bhi, Blo};
#pragma unroll
        for (int tile = 0; tile < 4; tile++) {
            const int rbase = (tile < 2) ? bm : bn;
            const uint32_t td = st + tile * TILE_B;
#pragma unroll
            for (int i = 0; i < 2; i++) {
                int p = tid + i * 128;
                int row = p >> 1, hf = p & 1;
                const __nv_bfloat16* g =
                    gp[tile] + (size_t)(rbase + row) * K + kc + hf * 16;
                uint32_t sd = td + row * ROWB + hf * 32;
                cpa16(sd, g);
                cpa16(sd + 16, g + 8);
            }
        }
        asm volatile("cp.async.commit_group;" ::: "memory");
    };

    const int KT = K / GBK;
    load_stage(0, 0);
    load_stage(1, 1);

    for (int kt = 0; kt < KT; kt++) {
        const int s = kt & 1;
        if (kt + 1 < KT)
            asm volatile("cp.async.wait_group 1;" ::: "memory");
        else
            asm volatile("cp.async.wait_group 0;" ::: "memory");
        __syncthreads();

        const uint32_t st = sb + s * STAGE_B;
        const uint32_t stAh = st, stAl = st + TILE_B;
        const uint32_t stBh = st + 2 * TILE_B, stBl = st + 3 * TILE_B;

#pragma unroll
        for (int ks = 0; ks < 2; ks++) {
            const uint32_t ko = ks * 32;
            uint32_t bh[4][4], bl[4][4], af[4][4];
#pragma unroll
            for (int p = 0; p < 4; p++)
                ldsm4(bh[p], stBh + boff + p * 16 * ROWB + ko);
#pragma unroll
            for (int m = 0; m < 4; m++)
                ldsm4(af[m], stAh + aoff + m * 16 * ROWB + ko);
#pragma unroll
            for (int n = 0; n < 8; n++)
#pragma unroll
                for (int m = 0; m < 4; m++)
                    mma16816(acc[m][n], af[m], &bh[n >> 1][(n & 1) * 2]);
#pragma unroll
            for (int p = 0; p < 4; p++)
                ldsm4(bl[p], stBl + boff + p * 16 * ROWB + ko);
#pragma unroll
            for (int n = 0; n < 8; n++)
#pragma unroll
                for (int m = 0; m < 4; m++)
                    mma16816(acc[m][n], af[m], &bl[n >> 1][(n & 1) * 2]);
#pragma unroll
            for (int m = 0; m < 4; m++)
                ldsm4(af[m], stAl + aoff + m * 16 * ROWB + ko);
#pragma unroll
            for (int n = 0; n < 8; n++)
#pragma unroll
                for (int m = 0; m < 4; m++)
                    mma16816(acc[m][n], af[m], &bh[n >> 1][(n & 1) * 2]);
        }
        __syncthreads();
        if (kt + 2 < KT) load_stage(s, kt + 2);
    }

    // Epilogue
    const int rql = lane >> 2, cql = (lane & 3) * 2;
#pragma unroll
    for (int m = 0; m < 4; m++) {
        const int row = bm + mbw + m * 16 + rql;
#pragma unroll
        for (int n = 0; n < 8; n++) {
            const int col = bn + nbw + n * 8 + cql;
            const float bx = bias[col], by = bias[col + 1];
            float v0 = acc[m][n][0] + bx, v1 = acc[m][n][1] + by;
            float v2 = acc[m][n][2] + bx, v3 = acc[m][n][3] + by;
            if (SPLIT_OUT) {
                uint32_t h01, l01, h23, l23;
                split2(v0, v1, h01, l01);
                split2(v2, v3, h23, l23);
                *(uint32_t*)(Chi + (size_t)row * N + col) = h01;
                *(uint32_t*)(Clo + (size_t)row * N + col) = l01;
                *(uint32_t*)(Chi + (size_t)(row + 8) * N + col) = h23;
                *(uint32_t*)(Clo + (size_t)(row + 8) * N + col) = l23;
            } else {
                *(float2*)(C + (size_t)row * N + col) = make_float2(v0, v1);
                *(float2*)(C + (size_t)(row + 8) * N + col) = make_float2(v2, v3);
            }
        }
    }
}

// ---------------------------------------------------------------------------
// HMMA flash attention with bf16 hi/lo split.
// CTA: 128 q rows x one (b,h); 8 warps x m16; KV tiles of 64, double-buffered.
// S = Qh*Kh + Qh*Kl + Ql*Kh (fp32 accum); online softmax in registers;
// P split hi/lo in registers (FA2 frag reuse); O += Ph*Vh + Pl*Vh + Ph*Vl.
// Output written directly as bf16 hi/lo for the proj GEMM.
//
// Smem: Qh/Ql [128][72*2B]=36864; 2 stages x (Kh,Kl,Vh,Vl [64][144B] + mask 256B)
//       = 2 x 37120;  total 111104 B.
// ---------------------------------------------------------------------------
#define AROW 144
#define ATT_QBYTES (128 * AROW)          // 18432
#define ATT_KVTILE (64 * AROW)           // 9216
#define ATT_STAGE (4 * ATT_KVTILE + 256) // 37120
#define ATT_SMEM (2 * ATT_QBYTES + 2 * ATT_STAGE)

__global__ __launch_bounds__(256) void attn_hmma(
    const __nv_bfloat16* __restrict__ qkv_hi,
    const __nv_bfloat16* __restrict__ qkv_lo,
    const float* __restrict__ mask,
    __nv_bfloat16* __restrict__ out_hi,
    __nv_bfloat16* __restrict__ out_lo)
{
    extern __shared__ char smc[];
    const uint32_t sb = smem_u32(smc);
    const int tid = threadIdx.x, lane = tid & 31, w = tid >> 5;
    const int qt = blockIdx.x * 128;
    const int h = blockIdx.y, b = blockIdx.z;

    // ---- Q load (stays resident) ----
#pragma unroll
    for (int i = 0; i < 8; i++) {
        int idx = tid + i * 256;                // 0..2047
        int half = idx >> 10;                   // 0=hi 1=lo
        int rem = idx & 1023;
        int row = rem >> 3, c = rem & 7;
        const __nv_bfloat16* g = (half ? qkv_lo : qkv_hi) +
            (size_t)(b * T_SEQ + qt + row) * 3072 + h * 64 + c * 8;
        cpa16(sb + half * ATT_QBYTES + row * AROW + c * 16, g);
    }

    const uint32_t stg0 = sb + 2 * ATT_QBYTES;

    auto load_kv = [&](int s, int kt) {
        const uint32_t st = stg0 + s * ATT_STAGE;
#pragma unroll
        for (int i = 0; i < 8; i++) {
            int idx = tid + i * 256;
            int tile = idx >> 9;                // 0:Kh 1:Kl 2:Vh 3:Vl
            int rem = idx & 511;
            int row = rem >> 3, c = rem & 7;
            int coff = ((tile < 2) ? 1024 : 2048) + h * 64;
            const __nv_bfloat16* g = ((tile & 1) ? qkv_lo : qkv_hi) +
                (size_t)(b * T_SEQ + kt * 64 + row) * 3072 + coff + c * 8;
            cpa16(st + tile * ATT_KVTILE + row * AROW + c * 16, g);
        }
        if (tid < 16)
            cpa16(st + 4 * ATT_KVTILE + tid * 16,
                  mask + (size_t)b * T_SEQ + kt * 64 + tid * 4);
        asm volatile("cp.async.commit_group;" ::: "memory");
    };

    load_kv(0, 0);   // group 0 also covers Q
    asm volatile("cp.async.commit_group;" ::: "memory"); // flush (Q was pre-group; safe)
    load_kv(1, 1);

    // frag base offsets
    const uint32_t aoffQ = (uint32_t)(w * 16 + (lane & 15)) * AROW +
                           (uint32_t)(lane >> 4) * 16;
    const uint32_t boffK = (uint32_t)((lane >> 4) * 8 + (lane & 7)) * AROW +
                           (uint32_t)((lane >> 3) & 1) * 16;
    const uint32_t voffV = (uint32_t)(lane & 15) * AROW +
                           (uint32_t)(lane >> 4) * 16;

    float mst0 = -1e30f, mst1 = -1e30f, lst0 = 0.f, lst1 = 0.f;
    float O[8][4];
#pragma unroll
    for (int n = 0; n < 8; n++)
#pragma unroll
        for (int j = 0; j < 4; j++) O[n][j] = 0.f;

    const int NKV = T_SEQ / 64;     // 32
    for (int kt = 0; kt < NKV; kt++) {
        const int s = kt & 1;
        if (kt + 1 < NKV)
            asm volatile("cp.async.wait_group 1;" ::: "memory");
        else
            asm volatile("cp.async.wait_group 0;" ::: "memory");
        __syncthreads();

        const uint32_t st = stg0 + s * ATT_STAGE;
        const float* mskp = (const float*)(smc + 2 * ATT_QBYTES +
                                           s * ATT_STAGE + 4 * ATT_KVTILE);

        // ---- S = Q K^T (3-term) ----
        float S[8][4];
#pragma unroll
        for (int n = 0; n < 8; n++)
#pragma unroll
            for (int j = 0; j < 4; j++) S[n][j] = 0.f;

#pragma unroll
        for (int kg = 0; kg < 4; kg++) {
            uint32_t qh[4], ql[4];
            ldsm4(qh, sb + aoffQ + kg * 32);
            ldsm4(ql, sb + ATT_QBYTES + aoffQ + kg * 32);
#pragma unroll
            for (int nb = 0; nb < 4; nb++) {
                uint32_t kh[4], kl[4];
                ldsm4(kh, st + boffK + nb * 16 * AROW + kg * 32);
                ldsm4(kl, st + ATT_KVTILE + boffK + nb * 16 * AROW + kg * 32);
                mma16816(S[2 * nb],     qh, &kh[0]);
                mma16816(S[2 * nb + 1], qh, &kh[2]);
                mma16816(S[2 * nb],     qh, &kl[0]);
                mma16816(S[2 * nb + 1], qh, &kl[2]);
                mma16816(S[2 * nb],     ql, &kh[0]);
                mma16816(S[2 * nb + 1], ql, &kh[2]);
            }
        }

        // ---- scale + double mask + online softmax ----
        float mx0 = -1e30f, mx1 = -1e30f;
#pragma unroll
        for (int n = 0; n < 8; n++) {
            float2 mk = *(const float2*)(mskp + n * 8 + (lane & 3) * 2);
            float m0 = 2.f * mk.x, m1 = 2.f * mk.y;
            S[n][0] = fmaf(S[n][0], 0.125f, m0);
            S[n][1] = fmaf(S[n][1], 0.125f, m1);
            S[n][2] = fmaf(S[n][2], 0.125f, m0);
            S[n][3] = fmaf(S[n][3], 0.125f, m1);
            mx0 = fmaxf(mx0, fmaxf(S[n][0], S[n][1]));
            mx1 = fmaxf(mx1, fmaxf(S[n][2], S[n][3]));
        }
        mx0 = fmaxf(mx0, __shfl_xor_sync(0xffffffffu, mx0, 1));
        mx0 = fmaxf(mx0, __shfl_xor_sync(0xffffffffu, mx0, 2));
        mx1 = fmaxf(mx1, __shfl_xor_sync(0xffffffffu, mx1, 1));
        mx1 = fmaxf(mx1, __shfl_xor_sync(0xffffffffu, mx1, 2));

        const float mn0 = fmaxf(mst0, mx0), mn1 = fmaxf(mst1, mx1);
        const float cr0 = __expf(mst0 - mn0), cr1 = __expf(mst1 - mn1);
        mst0 = mn0; mst1 = mn1;

        float rs0 = 0.f, rs1 = 0.f;
#pragma unroll
        for (int n = 0; n < 8; n++) {
            S[n][0] = __expf(S[n][0] - mn0);
            S[n][1] = __expf(S[n][1] - mn0);
            S[n][2] = __expf(S[n][2] - mn1);
            S[n][3] = __expf(S[n][3] - mn1);
            rs0 += S[n][0] + S[n][1];
            rs1 += S[n][2] + S[n][3];
        }
        rs0 += __shfl_xor_sync(0xffffffffu, rs0, 1);
        rs0 += __shfl_xor_sync(0xffffffffu, rs0, 2);
        rs1 += __shfl_xor_sync(0xffffffffu, rs1, 1);
        rs1 += __shfl_xor_sync(0xffffffffu, rs1, 2);
        lst0 = lst0 * cr0 + rs0;
        lst1 = lst1 * cr1 + rs1;

#pragma unroll
        for (int n = 0; n < 8; n++) {
            O[n][0] *= cr0; O[n][1] *= cr0;
            O[n][2] *= cr1; O[n][3] *= cr1;
        }

        // ---- O += P V (3-term, P frags built in registers) ----
#pragma unroll
        for (int kg = 0; kg < 4; kg++) {
            uint32_t ah[4], al[4];
            split2(S[2 * kg][0],     S[2 * kg][1],     ah[0], al[0]);
            split2(S[2 * kg][2],     S[2 * kg][3],     ah[1], al[1]);
            split2(S[2 * kg + 1][0], S[2 * kg + 1][1], ah[2], al[2]);
            split2(S[2 * kg + 1][2], S[2 * kg + 1][3], ah[3], al[3]);
#pragma unroll
            for (int nb = 0; nb < 4; nb++) {
                uint32_t vh[4], vl[4];
                ldsm4t(vh, st + 2 * ATT_KVTILE + voffV + kg * 16 * AROW + nb * 32);
                ldsm4t(vl, st + 3 * ATT_KVTILE + voffV + kg * 16 * AROW + nb * 32);
                mma16816(O[2 * nb],     ah, &vh[0]);
                mma16816(O[2 * nb + 1], ah, &vh[2]);
                mma16816(O[2 * nb],     al, &vh[0]);
                mma16816(O[2 * nb + 1], al, &vh[2]);
                mma16816(O[2 * nb],     ah, &vl[0]);
                mma16816(O[2 * nb + 1], ah, &vl[2]);
            }
        }
        __syncthreads();
        if (kt + 2 < NKV) load_kv(s, kt + 2);
    }

    // ---- epilogue: normalize, split, store bf16 hi/lo ----
    const float inv0 = 1.f / lst0, inv1 = 1.f / lst1;
    const int row0 = b * T_SEQ + qt + w * 16 + (lane >> 2);
    const int colb = h * 64 + (lane & 3) * 2;
#pragma unroll
    for (int n = 0; n < 8; n++) {
        uint32_t h01, l01, h23, l23;
        split2(O[n][0] * inv0, O[n][1] * inv0, h01, l01);
        split2(O[n][2] * inv1, O[n][3] * inv1, h23, l23);
        const size_t o0 = (size_t)row0 * D_MODEL + colb + n * 8;
        const size_t o1 = (size_t)(row0 + 8) * D_MODEL + colb + n * 8;
        *(uint32_t*)(out_hi + o0) = h01;
        *(uint32_t*)(out_lo + o0) = l01;
        *(uint32_t*)(out_hi + o1) = h23;
        *(uint32_t*)(out_lo + o1) = l23;
    }
}

// ---------------------------------------------------------------------------
extern "C" void kernel_launch(void* const* d_in, const int* in_sizes, int n_in,
                              void* d_out, int out_size)
{
    const float* x      = (const float*)d_in[0];
    const float* mask   = (const float*)d_in[1];
    const float* w_attn = (const float*)d_in[2];
    const float* b_attn = (const float*)d_in[3];
    const float* w_proj = (const float*)d_in[4];
    const float* b_proj = (const float*)d_in[5];
    float* out = (float*)d_out;

    __nv_bfloat16 *qkv_hi, *qkv_lo, *att_hi, *att_lo;
    __nv_bfloat16 *xa_hi, *xa_lo, *wa_hi, *wa_lo, *wp_hi, *wp_lo;
    cudaGetSymbolAddress((void**)&qkv_hi, g_qkv_hi);
    cudaGetSymbolAddress((void**)&qkv_lo, g_qkv_lo);
    cudaGetSymbolAddress((void**)&att_hi, g_att_hi);
    cudaGetSymbolAddress((void**)&att_lo, g_att_lo);
    cudaGetSymbolAddress((void**)&xa_hi, g_xa_hi);
    cudaGetSymbolAddress((void**)&xa_lo, g_xa_lo);
    cudaGetSymbolAddress((void**)&wa_hi, g_wa_hi);
    cudaGetSymbolAddress((void**)&wa_lo, g_wa_lo);
    cudaGetSymbolAddress((void**)&wp_hi, g_wp_hi);
    cudaGetSymbolAddress((void**)&wp_lo, g_wp_lo);

    cudaFuncSetAttribute(gemm_hmma<0>,
                         cudaFuncAttributeMaxDynamicSharedMemorySize, GEMM_SMEM);
    cudaFuncSetAttribute(gemm_hmma<1>,
                         cudaFuncAttributeMaxDynamicSharedMemorySize, GEMM_SMEM);
    cudaFuncSetAttribute(attn_hmma,
                         cudaFuncAttributeMaxDynamicSharedMemorySize, ATT_SMEM);

    const int nx = BT_ROWS * 1024;

    // 1) splits of inputs/weights
    split_mat<<<nx / 4 / 256, 256>>>(x, xa_hi, xa_lo, nx);
    split_wT<<<dim3(3072 / 32, 1024 / 32), dim3(32, 8)>>>(w_attn, wa_hi, wa_lo, 1024, 3072);
    split_wT<<<dim3(1024 / 32, 1024 / 32), dim3(32, 8)>>>(w_proj, wp_hi, wp_lo, 1024, 1024);

    // 2) qkv = x @ w_attn + b_attn  -> bf16 hi/lo (fused split epilogue)
    gemm_hmma<1><<<dim3(3072 / 128, BT_ROWS / 128), 128, GEMM_SMEM>>>(
        xa_hi, xa_lo, wa_hi, wa_lo, b_attn, nullptr, qkv_hi, qkv_lo, 3072, 1024);

    // 3) attention (HMMA, split precision) -> att hi/lo
    attn_hmma<<<dim3(T_SEQ / 128, 16, 2), 256, ATT_SMEM>>>(
        qkv_hi, qkv_lo, mask, att_hi, att_lo);

    // 4) out = att @ w_proj + b_proj (fp32 out)
    gemm_hmma<0><<<dim3(1024 / 128, BT_ROWS / 128), 128, GEMM_SMEM>>>(
        att_hi, att_lo, wp_hi, wp_lo, b_proj, out, nullptr, nullptr, 1024, 1024);
}